// round 2
// baseline (speedup 1.0000x reference)
#include <cuda_runtime.h>

// FourierLayer: out = relu(lw * Re(IFFT(FFT(x) * w)) + lw * x)
// Reduction: out = relu(lw * IFFT(FFT(x) * m)),  m[k] = (0.5*(w[k]+w[(N-k)%N]) + 1)/N
// m is real & even => operator maps real->real, so two rows pack into one complex FFT.

#define NFFT 4096
#define NPAIR 8192        // 16384 rows / 2
#define TPB 256           // threads per CTA; each thread owns 16 complex points
#define SH_PAD_SIZE 4352  // padded shared: idx = a + 17*b (a<16, b<256) max 4350

__device__ float g_m[NFFT];

__device__ __forceinline__ float2 cmulf(float2 a, float2 b) {
    return make_float2(a.x * b.x - a.y * b.y, a.x * b.y + a.y * b.x);
}

// trivial butterfly: a' = a+b, b' = a-b
__device__ __forceinline__ void bf(float2& a, float2& b) {
    float tx = a.x, ty = a.y;
    a.x = tx + b.x; a.y = ty + b.y;
    b.x = tx - b.x; b.y = ty - b.y;
}
// butterfly with twiddle (wr, wi): b' = (a-b)*(wr + i*wi)
__device__ __forceinline__ void bfw(float2& a, float2& b, float wr, float wi) {
    float dx = a.x - b.x, dy = a.y - b.y;
    a.x += b.x; a.y += b.y;
    b.x = dx * wr - dy * wi;
    b.y = dx * wi + dy * wr;
}
// butterfly with twiddle (0, sg): b' = (a-b)*(i*sg)
__device__ __forceinline__ void bfj(float2& a, float2& b, float sg) {
    float dx = a.x - b.x, dy = a.y - b.y;
    a.x += b.x; a.y += b.y;
    b.x = -sg * dy;
    b.y = sg * dx;
}
__device__ __forceinline__ void swp(float2& a, float2& b) {
    float2 t = a; a = b; b = t;
}

// 16-point DFT in registers, DIF radix-2, natural-order output.
// SGN = -1: forward (e^{-2pi i nk/16}); SGN = +1: inverse direction (no 1/16).
template <int SGN>
__device__ __forceinline__ void fft16(float2* v) {
    const float sg  = (float)SGN;
    const float C8  = 0.70710678118654752f;  // cos(pi/4)
    const float C16 = 0.92387953251128674f;  // cos(pi/8)
    const float S16 = 0.38268343236508978f;  // sin(pi/8)

    // stage len=16: pairs (j, j+8), twiddle W16^j = (cos(pi j/8), sg*sin(pi j/8))
    bf (v[0], v[8]);
    bfw(v[1], v[9],  C16,  sg * S16);
    bfw(v[2], v[10], C8,   sg * C8);
    bfw(v[3], v[11], S16,  sg * C16);
    bfj(v[4], v[12], sg);
    bfw(v[5], v[13], -S16, sg * C16);
    bfw(v[6], v[14], -C8,  sg * C8);
    bfw(v[7], v[15], -C16, sg * S16);
    // stage len=8: twiddle W8^j
    bf (v[0], v[4]);  bfw(v[1], v[5],  C8, sg * C8);  bfj(v[2], v[6],  sg);  bfw(v[3], v[7],  -C8, sg * C8);
    bf (v[8], v[12]); bfw(v[9], v[13], C8, sg * C8);  bfj(v[10], v[14], sg); bfw(v[11], v[15], -C8, sg * C8);
    // stage len=4
    bf(v[0], v[2]);  bfj(v[1], v[3],  sg);
    bf(v[4], v[6]);  bfj(v[5], v[7],  sg);
    bf(v[8], v[10]); bfj(v[9], v[11], sg);
    bf(v[12], v[14]); bfj(v[13], v[15], sg);
    // stage len=2
    bf(v[0], v[1]); bf(v[2], v[3]); bf(v[4], v[5]); bf(v[6], v[7]);
    bf(v[8], v[9]); bf(v[10], v[11]); bf(v[12], v[13]); bf(v[14], v[15]);
    // bit-reversal to natural order
    swp(v[1], v[8]); swp(v[2], v[4]); swp(v[3], v[12]);
    swp(v[5], v[10]); swp(v[7], v[14]); swp(v[11], v[13]);
}

// 4096-point FFT, N = 16^3 decomposition, 3 register passes + 2 shared exchanges.
// Input: thread tau holds v[r] = data[tau + 256*r] (natural order).
// Output: thread tau holds X[k] for k = (tau/16) + 16*(tau%16) + 256*r in v[r].
template <int SGN>
__device__ __forceinline__ void fft4096(float2* v, float2* sh, int tau) {
    const int lo = tau & 15;   // fine digit
    const int hi = tau >> 4;   // coarse digit
    const float TWO_PI = 6.28318530717958648f;

    // pass 1: DFT over coarse input digit (reg index)
    fft16<SGN>(v);
    // twiddle w256^{hi*r}, generated by geometric chain (1 sincos)
    {
        float ang = (float)SGN * TWO_PI * (float)hi * (1.0f / 256.0f);
        float s, c;
        __sincosf(ang, &s, &c);
        float2 wstep = make_float2(c, s);
        float2 wcur = wstep;
#pragma unroll
        for (int r = 1; r < 16; r++) {
            v[r] = cmulf(v[r], wcur);
            wcur = cmulf(wcur, wstep);
        }
    }
    // exchange 1
    __syncthreads();
#pragma unroll
    for (int r = 0; r < 16; r++) sh[lo + 17 * (hi + 16 * r)] = v[r];
    __syncthreads();
#pragma unroll
    for (int j = 0; j < 16; j++) v[j] = sh[lo + 17 * j + 272 * hi];

    // pass 2
    fft16<SGN>(v);
    // twiddle w4096^{lo*(hi + 16*f)} = base * step^f
    {
        float s, c;
        float angb = (float)SGN * TWO_PI * (float)(lo * hi) * (1.0f / 4096.0f);
        __sincosf(angb, &s, &c);
        float2 wcur = make_float2(c, s);
        float angs = (float)SGN * TWO_PI * (float)lo * (1.0f / 256.0f);
        __sincosf(angs, &s, &c);
        float2 wstep = make_float2(c, s);
        v[0] = cmulf(v[0], wcur);
#pragma unroll
        for (int f = 1; f < 16; f++) {
            wcur = cmulf(wcur, wstep);
            v[f] = cmulf(v[f], wcur);
        }
    }
    // exchange 2
    __syncthreads();
#pragma unroll
    for (int f = 0; f < 16; f++) sh[lo + 17 * (f + 16 * hi)] = v[f];
    __syncthreads();
#pragma unroll
    for (int j = 0; j < 16; j++) v[j] = sh[j + 17 * tau];

    // pass 3
    fft16<SGN>(v);
}

__global__ void prep_kernel(const float* __restrict__ fw) {
    int k = blockIdx.x * blockDim.x + threadIdx.x;
    if (k < NFFT) {
        float a = fw[k];
        float b = fw[(NFFT - k) & (NFFT - 1)];
        g_m[k] = (0.5f * (a + b) + 1.0f) * (1.0f / (float)NFFT);
    }
}

__global__ void __launch_bounds__(TPB)
fourier_kernel(const float* __restrict__ x, const float* __restrict__ lw,
               float* __restrict__ out) {
    __shared__ float2 sh[SH_PAD_SIZE];
    const int t = threadIdx.x;
    const size_t base = (size_t)blockIdx.x * (2 * NFFT);
    const float* row1 = x + base;
    const float* row2 = row1 + NFFT;

    float2 v[16];
#pragma unroll
    for (int r = 0; r < 16; r++)
        v[r] = make_float2(__ldg(row1 + t + 256 * r), __ldg(row2 + t + 256 * r));

    // forward FFT
    fft4096<-1>(v, sh, t);

    // spectral multiply: thread t, reg r holds k = (t/16) + 16*(t%16) + 256*r
    const int kbase = (t >> 4) + ((t & 15) << 4);
#pragma unroll
    for (int r = 0; r < 16; r++) {
        float mm = g_m[kbase + 256 * r];
        v[r].x *= mm;
        v[r].y *= mm;
    }

    // inverse FFT: relabel thread id by digit swap; output lands at n = t + 256*r
    const int tau = ((t & 15) << 4) | (t >> 4);
    fft4096<1>(v, sh, tau);

    float* o1 = out + base;
    float* o2 = o1 + NFFT;
#pragma unroll
    for (int r = 0; r < 16; r++) {
        float l = __ldg(lw + t + 256 * r);
        o1[t + 256 * r] = fmaxf(v[r].x * l, 0.0f);
        o2[t + 256 * r] = fmaxf(v[r].y * l, 0.0f);
    }
}

extern "C" void kernel_launch(void* const* d_in, const int* in_sizes, int n_in,
                              void* d_out, int out_size) {
    const float* x  = (const float*)d_in[0];
    const float* fw = (const float*)d_in[1];
    const float* lw = (const float*)d_in[2];
    float* out = (float*)d_out;

    prep_kernel<<<16, TPB>>>(fw);
    fourier_kernel<<<NPAIR, TPB>>>(x, lw, out);
}

// round 6
// speedup vs baseline: 2.9996x; 2.9996x over previous
#include <cuda_runtime.h>

// FourierLayer: out = relu(lw * Re(IFFT(FFT(x) * w)) + lw * x)
// Reduction: out = relu(lw * IFFT(FFT(x) * m)),  m[k] = (0.5*(w[k]+w[(N-k)%N]) + 1)/N
// m real & even => real->real operator; rows packed pairwise into complex FFTs.

#define NFFT 4096
#define NPAIR 8192        // 16384 rows / 2
#define TPB 256           // each thread owns 16 complex points
// layout L2(a,m) = a + 17*(m&15) + 273*(m>>4), a<16, m<256; max = 15+255+4095
#define SH_PAD_SIZE 4368

// Multiplier stored PERMUTED so the main kernel reads it coalesced:
// g_m[t + 256*r] = m[ nibbleswap(t) + 256*r ]
__device__ float g_m[NFFT];

__device__ __forceinline__ float2 cmulf(float2 a, float2 b) {
    return make_float2(a.x * b.x - a.y * b.y, a.x * b.y + a.y * b.x);
}
__device__ __forceinline__ void bf(float2& a, float2& b) {
    float tx = a.x, ty = a.y;
    a.x = tx + b.x; a.y = ty + b.y;
    b.x = tx - b.x; b.y = ty - b.y;
}
__device__ __forceinline__ void bfw(float2& a, float2& b, float wr, float wi) {
    float dx = a.x - b.x, dy = a.y - b.y;
    a.x += b.x; a.y += b.y;
    b.x = dx * wr - dy * wi;
    b.y = dx * wi + dy * wr;
}
__device__ __forceinline__ void bfj(float2& a, float2& b, float sg) {
    float dx = a.x - b.x, dy = a.y - b.y;
    a.x += b.x; a.y += b.y;
    b.x = -sg * dy;
    b.y = sg * dx;
}
__device__ __forceinline__ void swp(float2& a, float2& b) {
    float2 t = a; a = b; b = t;
}

// 16-point DFT in registers, DIF radix-2, natural-order output.
template <int SGN>
__device__ __forceinline__ void fft16(float2* v) {
    const float sg  = (float)SGN;
    const float C8  = 0.70710678118654752f;
    const float C16 = 0.92387953251128674f;
    const float S16 = 0.38268343236508978f;

    bf (v[0], v[8]);
    bfw(v[1], v[9],  C16,  sg * S16);
    bfw(v[2], v[10], C8,   sg * C8);
    bfw(v[3], v[11], S16,  sg * C16);
    bfj(v[4], v[12], sg);
    bfw(v[5], v[13], -S16, sg * C16);
    bfw(v[6], v[14], -C8,  sg * C8);
    bfw(v[7], v[15], -C16, sg * S16);

    bf (v[0], v[4]);  bfw(v[1], v[5],  C8, sg * C8);  bfj(v[2], v[6],  sg);  bfw(v[3], v[7],  -C8, sg * C8);
    bf (v[8], v[12]); bfw(v[9], v[13], C8, sg * C8);  bfj(v[10], v[14], sg); bfw(v[11], v[15], -C8, sg * C8);

    bf(v[0], v[2]);   bfj(v[1], v[3],  sg);
    bf(v[4], v[6]);   bfj(v[5], v[7],  sg);
    bf(v[8], v[10]);  bfj(v[9], v[11], sg);
    bf(v[12], v[14]); bfj(v[13], v[15], sg);

    bf(v[0], v[1]); bf(v[2], v[3]); bf(v[4], v[5]); bf(v[6], v[7]);
    bf(v[8], v[9]); bf(v[10], v[11]); bf(v[12], v[13]); bf(v[14], v[15]);

    swp(v[1], v[8]); swp(v[2], v[4]); swp(v[3], v[12]);
    swp(v[5], v[10]); swp(v[7], v[14]); swp(v[11], v[13]);
}

// Apply v[r] *= base * step^r for r = 0..15 (base may be (1,0)).
// Split-chain powering: two concurrent serial chains of depth ~7.
__device__ __forceinline__ void twiddle16(float2* v, float2 base, float2 step, bool mul_v0) {
    float2 s2 = cmulf(step, step);
    float2 s4 = cmulf(s2, s2);
    float2 s8 = cmulf(s4, s4);
    if (mul_v0) v[0] = cmulf(v[0], base);
    float2 lo = base;
    float2 hi8 = cmulf(base, s8);
    v[8] = cmulf(v[8], hi8);
#pragma unroll
    for (int j = 1; j < 8; j++) {
        lo = cmulf(lo, step);            // base*step^j
        v[j] = cmulf(v[j], lo);
        float2 hij = cmulf(lo, s8);      // base*step^(j+8)
        v[j + 8] = cmulf(v[j + 8], hij);
    }
}

// 4096-point FFT, 16^3 decomposition: 3 register passes + 2 shared exchanges.
// Shared layout L2(a, m) = a + 17*(m&15) + 273*(m>>4): conflict-free whether the
// in-phase varying digit of the thread label is lo (forward) or hi (inverse).
// Input: thread tau holds v[r] = data[tau + 256*r].
// Output: thread tau holds X[k], k = (tau>>4) + 16*(tau&15) + 256*r.
template <int SGN>
__device__ __forceinline__ void fft4096(float2* v, float2* sh, int tau) {
    const int lo = tau & 15;
    const int hi = tau >> 4;
    const float TWO_PI = 6.28318530717958648f;

    // pass 1
    fft16<SGN>(v);
    {
        float s, c;
        __sincosf((float)SGN * TWO_PI * (float)hi * (1.0f / 256.0f), &s, &c);
        twiddle16(v, make_float2(1.0f, 0.0f), make_float2(c, s), false);
    }
    // exchange 1: store L2(lo, hi + 16r), load L2(lo, j + 16hi)
    __syncthreads();
#pragma unroll
    for (int r = 0; r < 16; r++) sh[lo + 17 * hi + 273 * r] = v[r];
    __syncthreads();
#pragma unroll
    for (int j = 0; j < 16; j++) v[j] = sh[lo + 17 * j + 273 * hi];

    // pass 2
    fft16<SGN>(v);
    {
        float s, c;
        __sincosf((float)SGN * TWO_PI * (float)(lo * hi) * (1.0f / 4096.0f), &s, &c);
        float2 base = make_float2(c, s);
        __sincosf((float)SGN * TWO_PI * (float)lo * (1.0f / 256.0f), &s, &c);
        twiddle16(v, base, make_float2(c, s), true);
    }
    // exchange 2: store L2(lo, f + 16hi), load L2(j, lo + 16hi)
    __syncthreads();
#pragma unroll
    for (int f = 0; f < 16; f++) sh[lo + 17 * f + 273 * hi] = v[f];
    __syncthreads();
#pragma unroll
    for (int j = 0; j < 16; j++) v[j] = sh[j + 17 * lo + 273 * hi];

    // pass 3
    fft16<SGN>(v);
}

__global__ void prep_kernel(const float* __restrict__ fw) {
    int k = blockIdx.x * blockDim.x + threadIdx.x;
    if (k < NFFT) {
        // source index: nibble-swap the low byte (main kernel's in-register k map)
        int t = k & 255;
        int src = (k & ~255) | ((t >> 4) | ((t & 15) << 4));
        float a = fw[src];
        float b = fw[(NFFT - src) & (NFFT - 1)];
        g_m[k] = (0.5f * (a + b) + 1.0f) * (1.0f / (float)NFFT);
    }
}

__global__ void __launch_bounds__(TPB, 3)
fourier_kernel(const float* __restrict__ x, const float* __restrict__ lw,
               float* __restrict__ out) {
    __shared__ float2 sh[SH_PAD_SIZE];
    const int t = threadIdx.x;
    const size_t base = (size_t)blockIdx.x * (2 * NFFT);
    const float* row1 = x + base;
    const float* row2 = row1 + NFFT;

    float2 v[16];
#pragma unroll
    for (int r = 0; r < 16; r++)
        v[r] = make_float2(row1[t + 256 * r], row2[t + 256 * r]);

    // forward FFT
    fft4096<-1>(v, sh, t);

    // spectral multiply — g_m is pre-permuted, so this is fully coalesced
#pragma unroll
    for (int r = 0; r < 16; r++) {
        float mm = g_m[t + 256 * r];
        v[r].x *= mm;
        v[r].y *= mm;
    }

    // inverse FFT with digit-swapped thread label; output lands at n = t + 256*r
    const int tau = ((t & 15) << 4) | (t >> 4);
    fft4096<1>(v, sh, tau);

    float* o1 = out + base;
    float* o2 = o1 + NFFT;
#pragma unroll
    for (int r = 0; r < 16; r++) {
        float l = lw[t + 256 * r];
        o1[t + 256 * r] = fmaxf(v[r].x * l, 0.0f);
        o2[t + 256 * r] = fmaxf(v[r].y * l, 0.0f);
    }
}

extern "C" void kernel_launch(void* const* d_in, const int* in_sizes, int n_in,
                              void* d_out, int out_size) {
    const float* x  = (const float*)d_in[0];
    const float* fw = (const float*)d_in[1];
    const float* lw = (const float*)d_in[2];
    float* out = (float*)d_out;

    prep_kernel<<<16, TPB>>>(fw);
    fourier_kernel<<<NPAIR, TPB>>>(x, lw, out);
}

// round 12
// speedup vs baseline: 3.2095x; 1.0700x over previous
#include <cuda_runtime.h>

// FourierLayer: out = relu(lw * Re(IFFT(FFT(x) * w)) + lw * x)
// Reduction: out = relu(lw * IFFT(FFT(x) * m)),  m[k] = (0.5*(w[k]+w[(N-k)%N]) + 1)/N
// m real & even => real->real operator; rows packed pairwise into complex FFTs.

#define NFFT 4096
#define NPAIR 8192        // 16384 rows / 2
#define TPB 256           // each thread owns 16 complex points
// layout L2(a,m) = a + 17*(m&15) + 273*(m>>4), a<16, m<256; max = 15+255+4095
#define SH_PAD_SIZE 4368

// Multiplier stored PERMUTED so the main kernel reads it coalesced:
// g_m[t + 256*r] = m[ nibbleswap(t) + 256*r ]
__device__ float g_m[NFFT];

__device__ __forceinline__ void bf(float2& a, float2& b) {
    float tx = a.x, ty = a.y;
    a.x = tx + b.x; a.y = ty + b.y;
    b.x = tx - b.x; b.y = ty - b.y;
}
__device__ __forceinline__ void bfw(float2& a, float2& b, float wr, float wi) {
    float dx = a.x - b.x, dy = a.y - b.y;
    a.x += b.x; a.y += b.y;
    b.x = dx * wr - dy * wi;
    b.y = dx * wi + dy * wr;
}
__device__ __forceinline__ void bfj(float2& a, float2& b, float sg) {
    float dx = a.x - b.x, dy = a.y - b.y;
    a.x += b.x; a.y += b.y;
    b.x = -sg * dy;
    b.y = sg * dx;
}
__device__ __forceinline__ void swp(float2& a, float2& b) {
    float2 t = a; a = b; b = t;
}

// in-place multiply p *= (cos(ang), sin(ang)) via fast sincos (MUFU pipe)
__device__ __forceinline__ void twl(float2& p, float ang) {
    float s, c;
    __sincosf(ang, &s, &c);
    float nx = p.x * c - p.y * s;
    p.y = p.x * s + p.y * c;
    p.x = nx;
}

// 16-point DFT in registers, DIF radix-2, natural-order output.
template <int SGN>
__device__ __forceinline__ void fft16(float2* v) {
    const float sg  = (float)SGN;
    const float C8  = 0.70710678118654752f;
    const float C16 = 0.92387953251128674f;
    const float S16 = 0.38268343236508978f;

    bf (v[0], v[8]);
    bfw(v[1], v[9],  C16,  sg * S16);
    bfw(v[2], v[10], C8,   sg * C8);
    bfw(v[3], v[11], S16,  sg * C16);
    bfj(v[4], v[12], sg);
    bfw(v[5], v[13], -S16, sg * C16);
    bfw(v[6], v[14], -C8,  sg * C8);
    bfw(v[7], v[15], -C16, sg * S16);

    bf (v[0], v[4]);  bfw(v[1], v[5],  C8, sg * C8);  bfj(v[2], v[6],  sg);  bfw(v[3], v[7],  -C8, sg * C8);
    bf (v[8], v[12]); bfw(v[9], v[13], C8, sg * C8);  bfj(v[10], v[14], sg); bfw(v[11], v[15], -C8, sg * C8);

    bf(v[0], v[2]);   bfj(v[1], v[3],  sg);
    bf(v[4], v[6]);   bfj(v[5], v[7],  sg);
    bf(v[8], v[10]);  bfj(v[9], v[11], sg);
    bf(v[12], v[14]); bfj(v[13], v[15], sg);

    bf(v[0], v[1]); bf(v[2], v[3]); bf(v[4], v[5]); bf(v[6], v[7]);
    bf(v[8], v[9]); bf(v[10], v[11]); bf(v[12], v[13]); bf(v[14], v[15]);

    swp(v[1], v[8]); swp(v[2], v[4]); swp(v[3], v[12]);
    swp(v[5], v[10]); swp(v[7], v[14]); swp(v[11], v[13]);
}

// 4096-point FFT, 16^3 decomposition: 3 register passes + 2 shared exchanges.
// Shared layout L2(a, m) = a + 17*(m&15) + 273*(m>>4): conflict-free whether the
// in-phase varying digit of the thread label is lo (forward) or hi (inverse).
// Twiddles computed per-element on the MUFU pipe (no serial cmul chains).
// Input: thread tau holds v[r] = data[tau + 256*r].
// Output: thread tau holds X[k], k = (tau>>4) + 16*(tau&15) + 256*r.
template <int SGN>
__device__ __forceinline__ void fft4096(float2* v, float2* sh, int tau) {
    const int lo = tau & 15;
    const int hi = tau >> 4;
    const float TWO_PI = 6.28318530717958648f;

    // pass 1
    fft16<SGN>(v);
    {
        // v[r] *= exp(SGN*2pi*i * hi*r/256)
        const float A = (float)SGN * (TWO_PI / 256.0f) * (float)hi;
#pragma unroll
        for (int r = 1; r < 16; r++) twl(v[r], A * (float)r);
    }
    // exchange 1: store L2(lo, hi + 16r), load L2(lo, j + 16hi)
    __syncthreads();
#pragma unroll
    for (int r = 0; r < 16; r++) sh[lo + 17 * hi + 273 * r] = v[r];
    __syncthreads();
#pragma unroll
    for (int j = 0; j < 16; j++) v[j] = sh[lo + 17 * j + 273 * hi];

    // pass 2
    fft16<SGN>(v);
    {
        // v[f] *= exp(SGN*2pi*i * lo*(hi + 16f)/4096)
        const float A = (float)SGN * (TWO_PI / 256.0f) * (float)lo;
        const float B = (float)SGN * (TWO_PI / 4096.0f) * (float)(lo * hi);
#pragma unroll
        for (int f = 0; f < 16; f++) twl(v[f], fmaf((float)f, A, B));
    }
    // exchange 2: store L2(lo, f + 16hi), load L2(j, lo + 16hi)
    __syncthreads();
#pragma unroll
    for (int f = 0; f < 16; f++) sh[lo + 17 * f + 273 * hi] = v[f];
    __syncthreads();
#pragma unroll
    for (int j = 0; j < 16; j++) v[j] = sh[j + 17 * lo + 273 * hi];

    // pass 3
    fft16<SGN>(v);
}

__global__ void prep_kernel(const float* __restrict__ fw) {
    int k = blockIdx.x * blockDim.x + threadIdx.x;
    if (k < NFFT) {
        // source index: nibble-swap the low byte (main kernel's in-register k map)
        int t = k & 255;
        int src = (k & ~255) | ((t >> 4) | ((t & 15) << 4));
        float a = fw[src];
        float b = fw[(NFFT - src) & (NFFT - 1)];
        g_m[k] = (0.5f * (a + b) + 1.0f) * (1.0f / (float)NFFT);
    }
}

__global__ void __launch_bounds__(TPB, 4)
fourier_kernel(const float* __restrict__ x, const float* __restrict__ lw,
               float* __restrict__ out) {
    __shared__ float2 sh[SH_PAD_SIZE];
    const int t = threadIdx.x;
    const size_t base = (size_t)blockIdx.x * (2 * NFFT);
    const float* row1 = x + base;
    const float* row2 = row1 + NFFT;

    float2 v[16];
#pragma unroll
    for (int r = 0; r < 16; r++)
        v[r] = make_float2(row1[t + 256 * r], row2[t + 256 * r]);

    // forward FFT
    fft4096<-1>(v, sh, t);

    // spectral multiply — g_m is pre-permuted, so this is fully coalesced
#pragma unroll
    for (int r = 0; r < 16; r++) {
        float mm = g_m[t + 256 * r];
        v[r].x *= mm;
        v[r].y *= mm;
    }

    // inverse FFT with digit-swapped thread label; output lands at n = t + 256*r
    const int tau = ((t & 15) << 4) | (t >> 4);
    fft4096<1>(v, sh, tau);

    float* o1 = out + base;
    float* o2 = o1 + NFFT;
#pragma unroll
    for (int r = 0; r < 16; r++) {
        float l = lw[t + 256 * r];
        o1[t + 256 * r] = fmaxf(v[r].x * l, 0.0f);
        o2[t + 256 * r] = fmaxf(v[r].y * l, 0.0f);
    }
}

extern "C" void kernel_launch(void* const* d_in, const int* in_sizes, int n_in,
                              void* d_out, int out_size) {
    const float* x  = (const float*)d_in[0];
    const float* fw = (const float*)d_in[1];
    const float* lw = (const float*)d_in[2];
    float* out = (float*)d_out;

    prep_kernel<<<16, TPB>>>(fw);
    fourier_kernel<<<NPAIR, TPB>>>(x, lw, out);
}

// round 14
// speedup vs baseline: 3.4140x; 1.0637x over previous
#include <cuda_runtime.h>

// FourierLayer: out = relu(lw * Re(IFFT(FFT(x) * w)) + lw * x)
// Reduction: out = relu(lw * IFFT(FFT(x) * m)),  m[k] = (0.5*(w[k]+w[(N-k)%N]) + 1)/N
// m real & even => real->real operator; rows packed pairwise into complex FFTs.
// Butterfly add/sub acts componentwise on the packed pair -> f32x2 (FADD2/FFMA2).

#define NFFT 4096
#define NPAIR 8192        // 16384 rows / 2
#define TPB 256           // each thread owns 16 complex points
// layout L2(a,m) = a + 17*(m&15) + 273*(m>>4), a<16, m<256
#define SH_PAD_SIZE 4368

typedef unsigned long long u64;

__device__ float g_m[NFFT];  // permuted: g_m[t + 256*r] = m[nibbleswap(t) + 256*r]

// ---- packed f32x2 primitives (1 issue per 2 FLOPs) ----
__device__ __forceinline__ u64 pk(float x, float y) {
    u64 r; asm("mov.b64 %0,{%1,%2};" : "=l"(r) : "f"(x), "f"(y)); return r;
}
__device__ __forceinline__ void upk(u64 p, float& x, float& y) {
    asm("mov.b64 {%0,%1},%2;" : "=f"(x), "=f"(y) : "l"(p));
}
__device__ __forceinline__ u64 add2(u64 a, u64 b) {
    u64 r; asm("add.rn.f32x2 %0,%1,%2;" : "=l"(r) : "l"(a), "l"(b)); return r;
}
__device__ __forceinline__ u64 mul2(u64 a, u64 b) {
    u64 r; asm("mul.rn.f32x2 %0,%1,%2;" : "=l"(r) : "l"(a), "l"(b)); return r;
}
__device__ __forceinline__ u64 fma2(u64 a, u64 b, u64 c) {
    u64 r; asm("fma.rn.f32x2 %0,%1,%2,%3;" : "=l"(r) : "l"(a), "l"(b), "l"(c)); return r;
}
__device__ __forceinline__ float fneg(float x) {
    return __int_as_float(__float_as_int(x) ^ 0x80000000);  // alu pipe
}

#define NEG1_PK 0xBF800000BF800000ULL  // packed (-1.0f, -1.0f)

// a' = a+b ; b' = a-b   (2 packed issues)
__device__ __forceinline__ void bf(u64& a, u64& b) {
    u64 d = fma2(b, NEG1_PK, a);
    a = add2(a, b);
    b = d;
}
// b' = (a-b) * (wr + i*wi); rotation scalar with immediate constants (FFMA-imm rt=1)
__device__ __forceinline__ void bfw(u64& a, u64& b, float wr, float wi) {
    u64 d = fma2(b, NEG1_PK, a);
    a = add2(a, b);
    float dx, dy; upk(d, dx, dy);
    b = pk(dx * wr - dy * wi, dx * wi + dy * wr);
}
// b' = (a-b) * (i*SGN):  SGN=-1 -> (dy, -dx);  SGN=+1 -> (-dy, dx)
template <int SGN>
__device__ __forceinline__ void bfj(u64& a, u64& b) {
    u64 d = fma2(b, NEG1_PK, a);
    a = add2(a, b);
    float dx, dy; upk(d, dx, dy);
    b = (SGN < 0) ? pk(dy, fneg(dx)) : pk(fneg(dy), dx);
}
__device__ __forceinline__ void swp(u64& a, u64& b) { u64 t = a; a = b; b = t; }

// p *= (cos(ang), sin(ang)) — sincos on the MUFU pipe
__device__ __forceinline__ void twl(u64& p, float ang) {
    float s, c;
    __sincosf(ang, &s, &c);
    float x, y; upk(p, x, y);
    p = pk(x * c - y * s, x * s + y * c);
}

// 16-point DFT in registers, DIF radix-2, natural-order output.
template <int SGN>
__device__ __forceinline__ void fft16(u64* v) {
    const float sg  = (float)SGN;
    const float C8  = 0.70710678118654752f;
    const float C16 = 0.92387953251128674f;
    const float S16 = 0.38268343236508978f;

    bf (v[0], v[8]);
    bfw(v[1], v[9],  C16,  sg * S16);
    bfw(v[2], v[10], C8,   sg * C8);
    bfw(v[3], v[11], S16,  sg * C16);
    bfj<SGN>(v[4], v[12]);
    bfw(v[5], v[13], -S16, sg * C16);
    bfw(v[6], v[14], -C8,  sg * C8);
    bfw(v[7], v[15], -C16, sg * S16);

    bf (v[0], v[4]);  bfw(v[1], v[5],  C8, sg * C8);  bfj<SGN>(v[2], v[6]);   bfw(v[3], v[7],  -C8, sg * C8);
    bf (v[8], v[12]); bfw(v[9], v[13], C8, sg * C8);  bfj<SGN>(v[10], v[14]); bfw(v[11], v[15], -C8, sg * C8);

    bf(v[0], v[2]);   bfj<SGN>(v[1], v[3]);
    bf(v[4], v[6]);   bfj<SGN>(v[5], v[7]);
    bf(v[8], v[10]);  bfj<SGN>(v[9], v[11]);
    bf(v[12], v[14]); bfj<SGN>(v[13], v[15]);

    bf(v[0], v[1]); bf(v[2], v[3]); bf(v[4], v[5]); bf(v[6], v[7]);
    bf(v[8], v[9]); bf(v[10], v[11]); bf(v[12], v[13]); bf(v[14], v[15]);

    swp(v[1], v[8]); swp(v[2], v[4]); swp(v[3], v[12]);
    swp(v[5], v[10]); swp(v[7], v[14]); swp(v[11], v[13]);
}

// 4096-point FFT, 16^3 decomposition: 3 register passes + 2 shared exchanges.
// Shared layout L2(a, m) = a + 17*(m&15) + 273*(m>>4): conflict-free whether the
// in-phase varying digit of the thread label is lo (forward) or hi (inverse).
// Input: thread tau holds v[r] = data[tau + 256*r].
// Output: thread tau holds X[k], k = (tau>>4) + 16*(tau&15) + 256*r.
template <int SGN>
__device__ __forceinline__ void fft4096(u64* v, u64* sh, int tau) {
    const int lo = tau & 15;
    const int hi = tau >> 4;
    const float TWO_PI = 6.28318530717958648f;

    // pass 1
    fft16<SGN>(v);
    {
        const float A = (float)SGN * (TWO_PI / 256.0f) * (float)hi;
#pragma unroll
        for (int r = 1; r < 16; r++) twl(v[r], A * (float)r);
    }
    __syncthreads();
#pragma unroll
    for (int r = 0; r < 16; r++) sh[lo + 17 * hi + 273 * r] = v[r];
    __syncthreads();
#pragma unroll
    for (int j = 0; j < 16; j++) v[j] = sh[lo + 17 * j + 273 * hi];

    // pass 2
    fft16<SGN>(v);
    {
        const float A = (float)SGN * (TWO_PI / 256.0f) * (float)lo;
        const float B = (float)SGN * (TWO_PI / 4096.0f) * (float)(lo * hi);
#pragma unroll
        for (int f = 0; f < 16; f++) twl(v[f], fmaf((float)f, A, B));
    }
    __syncthreads();
#pragma unroll
    for (int f = 0; f < 16; f++) sh[lo + 17 * f + 273 * hi] = v[f];
    __syncthreads();
#pragma unroll
    for (int j = 0; j < 16; j++) v[j] = sh[j + 17 * lo + 273 * hi];

    // pass 3
    fft16<SGN>(v);
}

__global__ void prep_kernel(const float* __restrict__ fw) {
    int k = blockIdx.x * blockDim.x + threadIdx.x;
    if (k < NFFT) {
        int t = k & 255;
        int src = (k & ~255) | ((t >> 4) | ((t & 15) << 4));
        float a = fw[src];
        float b = fw[(NFFT - src) & (NFFT - 1)];
        g_m[k] = (0.5f * (a + b) + 1.0f) * (1.0f / (float)NFFT);
    }
}

__global__ void __launch_bounds__(TPB, 4)
fourier_kernel(const float* __restrict__ x, const float* __restrict__ lw,
               float* __restrict__ out) {
    __shared__ u64 sh[SH_PAD_SIZE];
    const int t = threadIdx.x;
    const size_t base = (size_t)blockIdx.x * (2 * NFFT);
    const float* row1 = x + base;
    const float* row2 = row1 + NFFT;

    u64 v[16];
#pragma unroll
    for (int r = 0; r < 16; r++)
        v[r] = pk(row1[t + 256 * r], row2[t + 256 * r]);

    // forward FFT
    fft4096<-1>(v, sh, t);

    // spectral multiply — g_m pre-permuted (coalesced); packed scale
#pragma unroll
    for (int r = 0; r < 16; r++) {
        float mm = g_m[t + 256 * r];
        v[r] = mul2(v[r], pk(mm, mm));
    }

    // inverse FFT with digit-swapped thread label; output lands at n = t + 256*r
    const int tau = ((t & 15) << 4) | (t >> 4);
    fft4096<1>(v, sh, tau);

    float* o1 = out + base;
    float* o2 = o1 + NFFT;
#pragma unroll
    for (int r = 0; r < 16; r++) {
        float l = lw[t + 256 * r];
        float vx, vy; upk(v[r], vx, vy);
        o1[t + 256 * r] = fmaxf(vx * l, 0.0f);
        o2[t + 256 * r] = fmaxf(vy * l, 0.0f);
    }
}

extern "C" void kernel_launch(void* const* d_in, const int* in_sizes, int n_in,
                              void* d_out, int out_size) {
    const float* x  = (const float*)d_in[0];
    const float* fw = (const float*)d_in[1];
    const float* lw = (const float*)d_in[2];
    float* out = (float*)d_out;

    prep_kernel<<<16, TPB>>>(fw);
    fourier_kernel<<<NPAIR, TPB>>>(x, lw, out);
}